// round 1
// baseline (speedup 1.0000x reference)
#include <cuda_runtime.h>
#include <cstdint>
#include <math.h>

// Problem constants
namespace {
constexpr int B_  = 4;
constexpr int T_  = 2048;
constexpr int DM_ = 1024;
constexpr int H_  = 16;
constexpr int DH_ = 64;          // DK == DV
constexpr int M_  = B_ * T_;     // 8192

// Scratch (device globals: allocation-free rule)
__device__ float g_q[(size_t)B_ * H_ * T_ * DH_];
__device__ float g_k[(size_t)B_ * H_ * T_ * DH_];
__device__ float g_v[(size_t)B_ * H_ * T_ * DH_];
__device__ float g_o[(size_t)M_ * DM_];

__device__ __forceinline__ float f2tf32(float x) {
    uint32_t u;
    asm("cvt.rna.tf32.f32 %0, %1;" : "=r"(u) : "f"(x));
    return __uint_as_float(u);
}

__device__ __forceinline__ void mma_m16n8k8(float* c, const uint32_t* a, const uint32_t* b) {
    asm volatile(
        "mma.sync.aligned.m16n8k8.row.col.f32.tf32.tf32.f32 "
        "{%0,%1,%2,%3}, {%4,%5,%6,%7}, {%8,%9}, {%0,%1,%2,%3};\n"
        : "+f"(c[0]), "+f"(c[1]), "+f"(c[2]), "+f"(c[3])
        : "r"(a[0]), "r"(a[1]), "r"(a[2]), "r"(a[3]), "r"(b[0]), "r"(b[1]));
}

// ---------------------------------------------------------------------------
// GEMM: C[m, h*64 + n] = sum_k X[m,k] * W[k,n]   (tf32 mma, fp32 accumulate)
// mode 0/1/2: QKV projection. W = per-head [DM,64] slice (ldk=64), output into
//             g_q/g_k/g_v with [B,H,T,64] layout.
// mode 3:     output projection. W = Wo[1024,1024] (ldk=1024), X = g_o,
//             output = d_out [8192,1024] with bias.
// grid: (64 m-tiles of 128, 16 n-tiles/heads), 256 threads (8 warps, 4x2).
// ---------------------------------------------------------------------------
__global__ void __launch_bounds__(256) gemm_tf32(
    const float* __restrict__ Xin, const float* __restrict__ W,
    const float* __restrict__ bias, float* __restrict__ outp_param, int mode)
{
    __shared__ float Xs[128][36];   // 128 x 32 (+4 pad)
    __shared__ float Ws[32][68];    // 32 x 64 (+4 pad)

    const int tid  = threadIdx.x;
    const int lane = tid & 31, wid = tid >> 5;
    const int wm   = wid >> 1, wn = wid & 1;
    const int g    = lane >> 2, q = lane & 3;
    const int h    = blockIdx.y;
    const size_t mBase = (size_t)blockIdx.x * 128;

    const float* X  = (mode == 3) ? g_o : Xin;
    const float* Wp = (mode == 3) ? (W + (size_t)h * DH_)
                                  : (W + (size_t)h * DM_ * DH_);
    const int ldk   = (mode == 3) ? DM_ : DH_;
    float* outp;
    if      (mode == 0) outp = g_q;
    else if (mode == 1) outp = g_k;
    else if (mode == 2) outp = g_v;
    else                outp = outp_param;

    float acc[2][4][4];
#pragma unroll
    for (int i = 0; i < 2; i++)
#pragma unroll
        for (int j = 0; j < 4; j++)
#pragma unroll
            for (int r = 0; r < 4; r++) acc[i][j][r] = 0.f;

    for (int k0 = 0; k0 < DM_; k0 += 32) {
        // X tile: 128x32, float4 coalesced, tf32-round on store
#pragma unroll
        for (int i = 0; i < 4; i++) {
            int r  = (tid >> 3) + i * 32;
            int c4 = (tid & 7) * 4;
            float4 v = *reinterpret_cast<const float4*>(X + (mBase + r) * DM_ + k0 + c4);
            float4 t = make_float4(f2tf32(v.x), f2tf32(v.y), f2tf32(v.z), f2tf32(v.w));
            *reinterpret_cast<float4*>(&Xs[r][c4]) = t;
        }
        // W tile: 32x64
#pragma unroll
        for (int i = 0; i < 2; i++) {
            int idx = tid + i * 256;
            int kk  = idx >> 4;
            int n4  = (idx & 15) * 4;
            float4 v = *reinterpret_cast<const float4*>(Wp + (size_t)(k0 + kk) * ldk + n4);
            float4 t = make_float4(f2tf32(v.x), f2tf32(v.y), f2tf32(v.z), f2tf32(v.w));
            *reinterpret_cast<float4*>(&Ws[kk][n4]) = t;
        }
        __syncthreads();

#pragma unroll
        for (int ks = 0; ks < 32; ks += 8) {
            uint32_t a[2][4], b[4][2];
#pragma unroll
            for (int mf = 0; mf < 2; mf++) {
                int r = wm * 32 + mf * 16 + g;
                a[mf][0] = __float_as_uint(Xs[r][ks + q]);
                a[mf][1] = __float_as_uint(Xs[r + 8][ks + q]);
                a[mf][2] = __float_as_uint(Xs[r][ks + q + 4]);
                a[mf][3] = __float_as_uint(Xs[r + 8][ks + q + 4]);
            }
#pragma unroll
            for (int nf = 0; nf < 4; nf++) {
                int n = wn * 32 + nf * 8 + g;
                b[nf][0] = __float_as_uint(Ws[ks + q][n]);
                b[nf][1] = __float_as_uint(Ws[ks + q + 4][n]);
            }
#pragma unroll
            for (int mf = 0; mf < 2; mf++)
#pragma unroll
                for (int nf = 0; nf < 4; nf++)
                    mma_m16n8k8(acc[mf][nf], a[mf], b[nf]);
        }
        __syncthreads();
    }

    // writeback
#pragma unroll
    for (int mf = 0; mf < 2; mf++) {
#pragma unroll
        for (int rr = 0; rr < 2; rr++) {
            size_t row = mBase + wm * 32 + mf * 16 + g + rr * 8;
#pragma unroll
            for (int nf = 0; nf < 4; nf++) {
                int n = wn * 32 + nf * 8 + 2 * q;
                float v0 = acc[mf][nf][2 * rr + 0];
                float v1 = acc[mf][nf][2 * rr + 1];
                if (mode != 3) {
                    size_t bidx = row / T_;
                    size_t t    = row % T_;
                    size_t o    = ((bidx * H_ + h) * T_ + t) * DH_ + n;
                    outp[o] = v0; outp[o + 1] = v1;
                } else {
                    int col  = h * DH_ + n;
                    size_t o = row * DM_ + col;
                    outp[o]     = v0 + bias[col];
                    outp[o + 1] = v1 + bias[col + 1];
                }
            }
        }
    }
}

// ---------------------------------------------------------------------------
// Causal flash attention (tf32 mma). grid = (T/128, B*H), 256 threads.
// Each warp owns 16 query rows; online softmax; P -> per-warp SMEM -> PV mma.
// Output written to g_o in [B, T, H*DV] layout (ready for out-projection).
// ---------------------------------------------------------------------------
constexpr int ATTN_SMEM = (128 + 64 + 64 + 128) * 68 * 4;  // 104448 B

__global__ void __launch_bounds__(256) attn_tf32(float* __restrict__ Odummy)
{
    extern __shared__ float sm[];
    float (*Qs)[68] = reinterpret_cast<float(*)[68]>(sm);
    float (*Ks)[68] = reinterpret_cast<float(*)[68]>(sm + 128 * 68);
    float (*Vs)[68] = reinterpret_cast<float(*)[68]>(sm + 192 * 68);
    float (*Ps)[68] = reinterpret_cast<float(*)[68]>(sm + 256 * 68);
    (void)Odummy;

    const int tid  = threadIdx.x;
    const int lane = tid & 31, wid = tid >> 5;
    const int g    = lane >> 2, q = lane & 3;
    const int wr   = wid * 16;
    const int bh   = blockIdx.y;
    const int qb   = blockIdx.x * 128;

    const float* Qg = g_q + ((size_t)bh * T_ + qb) * DH_;
    const float* Kg = g_k + (size_t)bh * T_ * DH_;
    const float* Vg = g_v + (size_t)bh * T_ * DH_;

    // Q tile 128x64
#pragma unroll
    for (int i = 0; i < 8; i++) {
        int idx = tid + i * 256;
        int r   = idx >> 4;
        int c4  = (idx & 15) * 4;
        float4 v = *reinterpret_cast<const float4*>(Qg + (size_t)r * DH_ + c4);
        *reinterpret_cast<float4*>(&Qs[r][c4]) =
            make_float4(f2tf32(v.x), f2tf32(v.y), f2tf32(v.z), f2tf32(v.w));
    }

    float o_acc[8][4];
#pragma unroll
    for (int i = 0; i < 8; i++)
#pragma unroll
        for (int r = 0; r < 4; r++) o_acc[i][r] = 0.f;
    float m0 = -INFINITY, m1 = -INFINITY, l0 = 0.f, l1 = 0.f;

    const int nkb = 2 * blockIdx.x + 2;  // key blocks of 64 covering [0, qb+128)
    for (int j = 0; j < nkb; j++) {
        __syncthreads();
        // K, V tiles 64x64 each
#pragma unroll
        for (int i = 0; i < 4; i++) {
            int idx = tid + i * 256;
            int r   = idx >> 4;
            int c4  = (idx & 15) * 4;
            size_t go = ((size_t)(j * 64 + r)) * DH_ + c4;
            float4 kv = *reinterpret_cast<const float4*>(Kg + go);
            *reinterpret_cast<float4*>(&Ks[r][c4]) =
                make_float4(f2tf32(kv.x), f2tf32(kv.y), f2tf32(kv.z), f2tf32(kv.w));
            float4 vv = *reinterpret_cast<const float4*>(Vg + go);
            *reinterpret_cast<float4*>(&Vs[r][c4]) =
                make_float4(f2tf32(vv.x), f2tf32(vv.y), f2tf32(vv.z), f2tf32(vv.w));
        }
        __syncthreads();

        // S = Q K^T  (per warp: 16 x 64)
        float s[8][4];
#pragma unroll
        for (int i = 0; i < 8; i++)
#pragma unroll
            for (int r = 0; r < 4; r++) s[i][r] = 0.f;

#pragma unroll
        for (int kk = 0; kk < 64; kk += 8) {
            uint32_t a[4];
            a[0] = __float_as_uint(Qs[wr + g][kk + q]);
            a[1] = __float_as_uint(Qs[wr + g + 8][kk + q]);
            a[2] = __float_as_uint(Qs[wr + g][kk + q + 4]);
            a[3] = __float_as_uint(Qs[wr + g + 8][kk + q + 4]);
#pragma unroll
            for (int nf = 0; nf < 8; nf++) {
                uint32_t b[2];
                b[0] = __float_as_uint(Ks[nf * 8 + g][kk + q]);
                b[1] = __float_as_uint(Ks[nf * 8 + g][kk + q + 4]);
                mma_m16n8k8(s[nf], a, b);
            }
        }

        const float scale = 0.125f;  // 1/sqrt(64)
        if (j >= nkb - 2) {          // blocks overlapping the diagonal
            const int row0 = qb + wr + g, row1 = row0 + 8;
#pragma unroll
            for (int nf = 0; nf < 8; nf++) {
                int c0 = j * 64 + nf * 8 + 2 * q;
                s[nf][0] = (c0     > row0) ? -INFINITY : s[nf][0] * scale;
                s[nf][1] = (c0 + 1 > row0) ? -INFINITY : s[nf][1] * scale;
                s[nf][2] = (c0     > row1) ? -INFINITY : s[nf][2] * scale;
                s[nf][3] = (c0 + 1 > row1) ? -INFINITY : s[nf][3] * scale;
            }
        } else {
#pragma unroll
            for (int nf = 0; nf < 8; nf++)
#pragma unroll
                for (int r = 0; r < 4; r++) s[nf][r] *= scale;
        }

        // online softmax (rows g and g+8; 4 lanes per row -> bfly reduce)
        float mloc0 = -INFINITY, mloc1 = -INFINITY;
#pragma unroll
        for (int nf = 0; nf < 8; nf++) {
            mloc0 = fmaxf(mloc0, fmaxf(s[nf][0], s[nf][1]));
            mloc1 = fmaxf(mloc1, fmaxf(s[nf][2], s[nf][3]));
        }
        mloc0 = fmaxf(mloc0, __shfl_xor_sync(0xffffffffu, mloc0, 1));
        mloc0 = fmaxf(mloc0, __shfl_xor_sync(0xffffffffu, mloc0, 2));
        mloc1 = fmaxf(mloc1, __shfl_xor_sync(0xffffffffu, mloc1, 1));
        mloc1 = fmaxf(mloc1, __shfl_xor_sync(0xffffffffu, mloc1, 2));

        float mn0 = fmaxf(m0, mloc0), mn1 = fmaxf(m1, mloc1);
        float al0 = __expf(m0 - mn0), al1 = __expf(m1 - mn1);
        float ls0 = 0.f, ls1 = 0.f;
#pragma unroll
        for (int nf = 0; nf < 8; nf++) {
            s[nf][0] = __expf(s[nf][0] - mn0);
            s[nf][1] = __expf(s[nf][1] - mn0);
            s[nf][2] = __expf(s[nf][2] - mn1);
            s[nf][3] = __expf(s[nf][3] - mn1);
            ls0 += s[nf][0] + s[nf][1];
            ls1 += s[nf][2] + s[nf][3];
        }
        ls0 += __shfl_xor_sync(0xffffffffu, ls0, 1);
        ls0 += __shfl_xor_sync(0xffffffffu, ls0, 2);
        ls1 += __shfl_xor_sync(0xffffffffu, ls1, 1);
        ls1 += __shfl_xor_sync(0xffffffffu, ls1, 2);

        l0 = l0 * al0 + ls0; l1 = l1 * al1 + ls1;
        m0 = mn0; m1 = mn1;
#pragma unroll
        for (int nf = 0; nf < 8; nf++) {
            o_acc[nf][0] *= al0; o_acc[nf][1] *= al0;
            o_acc[nf][2] *= al1; o_acc[nf][3] *= al1;
        }

        // P (tf32) -> per-warp SMEM (fragment layout fix for PV mma)
#pragma unroll
        for (int nf = 0; nf < 8; nf++) {
            int c0 = nf * 8 + 2 * q;
            Ps[wr + g][c0]         = f2tf32(s[nf][0]);
            Ps[wr + g][c0 + 1]     = f2tf32(s[nf][1]);
            Ps[wr + g + 8][c0]     = f2tf32(s[nf][2]);
            Ps[wr + g + 8][c0 + 1] = f2tf32(s[nf][3]);
        }
        __syncwarp();

        // O += P V
#pragma unroll
        for (int kk = 0; kk < 64; kk += 8) {
            uint32_t a[4];
            a[0] = __float_as_uint(Ps[wr + g][kk + q]);
            a[1] = __float_as_uint(Ps[wr + g + 8][kk + q]);
            a[2] = __float_as_uint(Ps[wr + g][kk + q + 4]);
            a[3] = __float_as_uint(Ps[wr + g + 8][kk + q + 4]);
#pragma unroll
            for (int nf = 0; nf < 8; nf++) {
                uint32_t b[2];
                b[0] = __float_as_uint(Vs[kk + q][nf * 8 + g]);
                b[1] = __float_as_uint(Vs[kk + q + 4][nf * 8 + g]);
                mma_m16n8k8(o_acc[nf], a, b);
            }
        }
    }

    // epilogue: normalize, write to g_o in [B, T, H*DV]
    const float inv0 = 1.f / l0, inv1 = 1.f / l1;
    const int b = bh / H_, h = bh % H_;
    const int t0 = qb + wr + g;
#pragma unroll
    for (int nf = 0; nf < 8; nf++) {
        int col   = h * DH_ + nf * 8 + 2 * q;
        size_t o0 = ((size_t)(b * T_ + t0)) * DM_ + col;
        size_t o1 = ((size_t)(b * T_ + t0 + 8)) * DM_ + col;
        g_o[o0]     = o_acc[nf][0] * inv0;
        g_o[o0 + 1] = o_acc[nf][1] * inv0;
        g_o[o1]     = o_acc[nf][2] * inv1;
        g_o[o1 + 1] = o_acc[nf][3] * inv1;
    }
}

}  // namespace

extern "C" void kernel_launch(void* const* d_in, const int* in_sizes, int n_in,
                              void* d_out, int out_size)
{
    (void)in_sizes; (void)n_in; (void)out_size;
    const float* x  = (const float*)d_in[0];
    const float* Wq = (const float*)d_in[1];
    const float* Wk = (const float*)d_in[2];
    const float* Wv = (const float*)d_in[3];
    const float* Wo = (const float*)d_in[4];
    const float* bo = (const float*)d_in[5];
    float* out = (float*)d_out;

    cudaFuncSetAttribute(attn_tf32, cudaFuncAttributeMaxDynamicSharedMemorySize, ATTN_SMEM);

    dim3 gg(M_ / 128, H_);
    gemm_tf32<<<gg, 256>>>(x, Wq, nullptr, nullptr, 0);
    gemm_tf32<<<gg, 256>>>(x, Wk, nullptr, nullptr, 1);
    gemm_tf32<<<gg, 256>>>(x, Wv, nullptr, nullptr, 2);
    attn_tf32<<<dim3(T_ / 128, B_ * H_), 256, ATTN_SMEM>>>(nullptr);
    gemm_tf32<<<gg, 256>>>(nullptr, Wo, bo, out, 3);
}

// round 2
// speedup vs baseline: 1.3489x; 1.3489x over previous
#include <cuda_runtime.h>
#include <cstdint>
#include <math.h>

namespace {
constexpr int B_  = 4;
constexpr int T_  = 2048;
constexpr int DM_ = 1024;
constexpr int H_  = 16;
constexpr int DH_ = 64;
constexpr int M_  = B_ * T_;     // 8192

// Scratch (device globals: allocation-free rule). All tf32-pre-rounded copies.
__device__ float g_x [(size_t)M_ * DM_];
__device__ float g_wq[(size_t)H_ * DM_ * DH_];
__device__ float g_wk[(size_t)H_ * DM_ * DH_];
__device__ float g_wv[(size_t)H_ * DM_ * DH_];
__device__ float g_wo[(size_t)DM_ * DM_];
__device__ float g_q [(size_t)M_ * DM_];   // [B,H,T,64] == 8.4M elems
__device__ float g_k [(size_t)M_ * DM_];
__device__ float g_v [(size_t)M_ * DM_];
__device__ float g_o [(size_t)M_ * DM_];   // [B,T,H*64]

__device__ __forceinline__ float f2tf32(float x) {
    uint32_t u;
    asm("cvt.rna.tf32.f32 %0, %1;" : "=r"(u) : "f"(x));
    return __uint_as_float(u);
}
__device__ __forceinline__ uint32_t f2tf32u(float x) {
    uint32_t u;
    asm("cvt.rna.tf32.f32 %0, %1;" : "=r"(u) : "f"(x));
    return u;
}
__device__ __forceinline__ float fexp2(float x) {
    float y;
    asm("ex2.approx.f32 %0, %1;" : "=f"(y) : "f"(x));
    return y;
}
__device__ __forceinline__ void mma_m16n8k8(float* c, const uint32_t* a, const uint32_t* b) {
    asm volatile(
        "mma.sync.aligned.m16n8k8.row.col.f32.tf32.tf32.f32 "
        "{%0,%1,%2,%3}, {%4,%5,%6,%7}, {%8,%9}, {%0,%1,%2,%3};\n"
        : "+f"(c[0]), "+f"(c[1]), "+f"(c[2]), "+f"(c[3])
        : "r"(a[0]), "r"(a[1]), "r"(a[2]), "r"(a[3]), "r"(b[0]), "r"(b[1]));
}
__device__ __forceinline__ uint32_t smem_u32(const void* p) {
    return (uint32_t)__cvta_generic_to_shared(p);
}
__device__ __forceinline__ void cp16(uint32_t dst, const void* src) {
    asm volatile("cp.async.cg.shared.global [%0], [%1], 16;\n" :: "r"(dst), "l"(src));
}
__device__ __forceinline__ void cp_commit() {
    asm volatile("cp.async.commit_group;\n");
}
template <int N>
__device__ __forceinline__ void cp_wait() {
    asm volatile("cp.async.wait_group %0;\n" :: "n"(N));
}

// ---------------------------------------------------------------------------
// Pre-round fp32 -> tf32 copies (so cp.async can move pre-rounded data)
// ---------------------------------------------------------------------------
__global__ void __launch_bounds__(256) round_k(const float* __restrict__ in, int which, int n4)
{
    float* out = (which == 0) ? g_x  : (which == 1) ? g_wq :
                 (which == 2) ? g_wk : (which == 3) ? g_wv : g_wo;
    int i = blockIdx.x * blockDim.x + threadIdx.x;
    if (i < n4) {
        float4 v = reinterpret_cast<const float4*>(in)[i];
        reinterpret_cast<float4*>(out)[i] =
            make_float4(f2tf32(v.x), f2tf32(v.y), f2tf32(v.z), f2tf32(v.w));
    }
}

// ---------------------------------------------------------------------------
// GEMM, tile 128x128, warp 32x64, k-chunk 32, 2-stage cp.async pipeline.
// mode 0: QKV projection. grid (64, 8, 3). z selects Wq/Wk/Wv; by = 2 heads.
//         out -> g_q/g_k/g_v [B,H,T,64], tf32-rounded.
// mode 1: out projection. grid (64, 8, 1). X=g_o, W=g_wo, out=d_out + bias.
// ---------------------------------------------------------------------------
constexpr int XSTR = 36;    // 32 + 4 pad (floats)
constexpr int WSTR = 136;   // 128 + 8 pad (floats) -> stride%32 == 8, conflict-free
constexpr int GSTAGE = 128 * XSTR + 32 * WSTR;    // 8960 floats
constexpr int GEMM_SMEM = 2 * GSTAGE * 4;         // 71680 B

__device__ __forceinline__ void gemm_load_chunk(
    float* sm, int buf, const float* __restrict__ X, const float* __restrict__ W,
    size_t mBase, int by, int k0, int mode, int tid)
{
    float* Xb = sm + buf * GSTAGE;
    float* Wb = Xb + 128 * XSTR;
#pragma unroll
    for (int i = 0; i < 4; i++) {
        int idx = tid + i * 256;
        int r = idx >> 3, c4 = (idx & 7) * 4;
        cp16(smem_u32(Xb + r * XSTR + c4), X + (mBase + r) * DM_ + k0 + c4);
    }
#pragma unroll
    for (int i = 0; i < 4; i++) {
        int idx = tid + i * 256;
        int r = idx >> 5, c4 = (idx & 31) * 4;
        const float* src;
        if (mode == 0) {
            int c = by * 128 + c4;
            int h = c >> 6;
            src = W + ((size_t)h * DM_ + (k0 + r)) * DH_ + (c & 63);
        } else {
            src = W + (size_t)(k0 + r) * DM_ + by * 128 + c4;
        }
        cp16(smem_u32(Wb + r * WSTR + c4), src);
    }
    cp_commit();
}

__global__ void __launch_bounds__(256, 2) gemm2(
    int mode, const float* __restrict__ bias, float* __restrict__ out_param)
{
    extern __shared__ float sm[];
    const int tid  = threadIdx.x;
    const int lane = tid & 31, wid = tid >> 5;
    const int wm = wid >> 1, wn = wid & 1;
    const int g = lane >> 2, q = lane & 3;
    const size_t mBase = (size_t)blockIdx.x * 128;
    const int by = blockIdx.y;
    const int z  = blockIdx.z;

    const float* X = (mode == 0) ? g_x : g_o;
    const float* W = (mode == 0) ? ((z == 0) ? g_wq : (z == 1) ? g_wk : g_wv) : g_wo;

    float acc[2][8][4];
#pragma unroll
    for (int i = 0; i < 2; i++)
#pragma unroll
        for (int j = 0; j < 8; j++)
#pragma unroll
            for (int r = 0; r < 4; r++) acc[i][j][r] = 0.f;

    gemm_load_chunk(sm, 0, X, W, mBase, by, 0, mode, tid);
    int buf = 0;
    for (int k0 = 0; k0 < DM_; k0 += 32) {
        if (k0 + 32 < DM_) {
            gemm_load_chunk(sm, buf ^ 1, X, W, mBase, by, k0 + 32, mode, tid);
            cp_wait<1>();
        } else {
            cp_wait<0>();
        }
        __syncthreads();
        const float* Xb = sm + buf * GSTAGE;
        const float* Wb = Xb + 128 * XSTR;
#pragma unroll
        for (int ks = 0; ks < 4; ks++) {
            uint32_t a[2][4];
#pragma unroll
            for (int mf = 0; mf < 2; mf++) {
                const float* xr = Xb + (wm * 32 + mf * 16 + g) * XSTR + ks * 8 + q;
                a[mf][0] = __float_as_uint(xr[0]);
                a[mf][1] = __float_as_uint(xr[8 * XSTR]);
                a[mf][2] = __float_as_uint(xr[4]);
                a[mf][3] = __float_as_uint(xr[8 * XSTR + 4]);
            }
            uint32_t b[8][2];
#pragma unroll
            for (int nf = 0; nf < 8; nf++) {
                int n = wn * 64 + nf * 8 + g;
                b[nf][0] = __float_as_uint(Wb[(ks * 8 + q) * WSTR + n]);
                b[nf][1] = __float_as_uint(Wb[(ks * 8 + q + 4) * WSTR + n]);
            }
#pragma unroll
            for (int mf = 0; mf < 2; mf++)
#pragma unroll
                for (int nf = 0; nf < 8; nf++)
                    mma_m16n8k8(acc[mf][nf], a[mf], b[nf]);
        }
        __syncthreads();
        buf ^= 1;
    }

    if (mode == 0) {
        float* outp = (z == 0) ? g_q : (z == 1) ? g_k : g_v;
#pragma unroll
        for (int mf = 0; mf < 2; mf++)
#pragma unroll
            for (int rr = 0; rr < 2; rr++) {
                size_t row = mBase + wm * 32 + mf * 16 + g + rr * 8;
                int bb = (int)(row >> 11), t = (int)(row & 2047);
#pragma unroll
                for (int nf = 0; nf < 8; nf++) {
                    int c = by * 128 + wn * 64 + nf * 8 + 2 * q;
                    int h = c >> 6, cc = c & 63;
                    size_t o = (((size_t)bb * H_ + h) * T_ + t) * DH_ + cc;
                    outp[o]     = f2tf32(acc[mf][nf][2 * rr + 0]);
                    outp[o + 1] = f2tf32(acc[mf][nf][2 * rr + 1]);
                }
            }
    } else {
#pragma unroll
        for (int mf = 0; mf < 2; mf++)
#pragma unroll
            for (int rr = 0; rr < 2; rr++) {
                size_t row = mBase + wm * 32 + mf * 16 + g + rr * 8;
#pragma unroll
                for (int nf = 0; nf < 8; nf++) {
                    int c = by * 128 + wn * 64 + nf * 8 + 2 * q;
                    size_t o = row * DM_ + c;
                    out_param[o]     = acc[mf][nf][2 * rr + 0] + bias[c];
                    out_param[o + 1] = acc[mf][nf][2 * rr + 1] + bias[c + 1];
                }
            }
    }
}

// ---------------------------------------------------------------------------
// Causal flash attention. CTA = 256 Q rows (8 warps x 32 rows), key blocks
// of 64, cp.async double-buffered K/V, Q frags in registers, P via shuffles.
// grid (T/256=8, B*H=64), 256 threads.
// ---------------------------------------------------------------------------
constexpr int KSTR = 68;    // 64 + 4 pad
constexpr int VSTR = 72;    // 64 + 8 pad (stride%32 == 8 for q-row indexing)
constexpr int ASTAGE = 64 * KSTR + 64 * VSTR;    // 8960 floats
constexpr int ATT_SMEM = 2 * ASTAGE * 4;         // 71680 B

__device__ __forceinline__ void attn_load_kv(
    float* sm, int buf, const float* __restrict__ Kg, const float* __restrict__ Vg,
    int j, int tid)
{
    float* Kb = sm + buf * ASTAGE;
    float* Vb = Kb + 64 * KSTR;
#pragma unroll
    for (int i = 0; i < 4; i++) {
        int idx = tid + i * 256;
        int r = idx >> 4, c4 = (idx & 15) * 4;
        cp16(smem_u32(Kb + r * KSTR + c4), Kg + (size_t)(j * 64 + r) * DH_ + c4);
    }
#pragma unroll
    for (int i = 0; i < 4; i++) {
        int idx = tid + i * 256;
        int r = idx >> 4, c4 = (idx & 15) * 4;
        cp16(smem_u32(Vb + r * VSTR + c4), Vg + (size_t)(j * 64 + r) * DH_ + c4);
    }
    cp_commit();
}

__global__ void __launch_bounds__(256, 1) attn2()
{
    extern __shared__ float sm[];
    const int tid  = threadIdx.x;
    const int lane = tid & 31, w = tid >> 5;
    const int g = lane >> 2, q = lane & 3;
    const int bx = (int)gridDim.x - 1 - (int)blockIdx.x;   // heavy CTAs first
    const int bh = blockIdx.y;
    const int qb = bx * 256;

    const float* Qg = g_q + ((size_t)bh * T_ + qb) * DH_;
    const float* Kg = g_k + (size_t)bh * T_ * DH_;
    const float* Vg = g_v + (size_t)bh * T_ * DH_;

    // Q fragments -> registers (pre-rounded tf32 bits)
    uint32_t qf[2][8][4];
#pragma unroll
    for (int mf = 0; mf < 2; mf++) {
        int r = w * 32 + mf * 16 + g;
#pragma unroll
        for (int ks = 0; ks < 8; ks++) {
            qf[mf][ks][0] = __float_as_uint(__ldg(Qg + (size_t)r * DH_ + ks * 8 + q));
            qf[mf][ks][1] = __float_as_uint(__ldg(Qg + (size_t)(r + 8) * DH_ + ks * 8 + q));
            qf[mf][ks][2] = __float_as_uint(__ldg(Qg + (size_t)r * DH_ + ks * 8 + q + 4));
            qf[mf][ks][3] = __float_as_uint(__ldg(Qg + (size_t)(r + 8) * DH_ + ks * 8 + q + 4));
        }
    }

    float o_acc[2][8][4];
#pragma unroll
    for (int i = 0; i < 2; i++)
#pragma unroll
        for (int j = 0; j < 8; j++)
#pragma unroll
            for (int r = 0; r < 4; r++) o_acc[i][j][r] = 0.f;
    float mx[2][2] = {{-INFINITY, -INFINITY}, {-INFINITY, -INFINITY}};
    float lsum[2][2] = {{0.f, 0.f}, {0.f, 0.f}};

    const int nkb = 4 * bx + 4;
    attn_load_kv(sm, 0, Kg, Vg, 0, tid);
    int buf = 0;
    for (int j = 0; j < nkb; j++) {
        if (j + 1 < nkb) {
            attn_load_kv(sm, buf ^ 1, Kg, Vg, j + 1, tid);
            cp_wait<1>();
        } else {
            cp_wait<0>();
        }
        __syncthreads();
        const float* Kb = sm + buf * ASTAGE;
        const float* Vb = Kb + 64 * KSTR;

        // S = Q K^T : per warp 32x64
        float s[2][8][4];
#pragma unroll
        for (int i = 0; i < 2; i++)
#pragma unroll
            for (int jj = 0; jj < 8; jj++)
#pragma unroll
                for (int r = 0; r < 4; r++) s[i][jj][r] = 0.f;

#pragma unroll
        for (int ks = 0; ks < 8; ks++) {
            uint32_t bk[8][2];
#pragma unroll
            for (int nf = 0; nf < 8; nf++) {
                bk[nf][0] = __float_as_uint(Kb[(nf * 8 + g) * KSTR + ks * 8 + q]);
                bk[nf][1] = __float_as_uint(Kb[(nf * 8 + g) * KSTR + ks * 8 + q + 4]);
            }
#pragma unroll
            for (int mf = 0; mf < 2; mf++)
#pragma unroll
                for (int nf = 0; nf < 8; nf++)
                    mma_m16n8k8(s[mf][nf], qf[mf][ks], bk[nf]);
        }

        // scale (folded to log2 domain) + causal mask + online softmax
        const float SCL = 0.18033688f;   // 0.125 * log2(e)
        const bool need_mask = (j * 64 + 63) > (qb + w * 32);
#pragma unroll
        for (int mf = 0; mf < 2; mf++) {
            const int row0 = qb + w * 32 + mf * 16 + g;
            if (need_mask) {
#pragma unroll
                for (int nf = 0; nf < 8; nf++) {
                    int c0 = j * 64 + nf * 8 + 2 * q;
                    s[mf][nf][0] = (c0     > row0)     ? -INFINITY : s[mf][nf][0] * SCL;
                    s[mf][nf][1] = (c0 + 1 > row0)     ? -INFINITY : s[mf][nf][1] * SCL;
                    s[mf][nf][2] = (c0     > row0 + 8) ? -INFINITY : s[mf][nf][2] * SCL;
                    s[mf][nf][3] = (c0 + 1 > row0 + 8) ? -INFINITY : s[mf][nf][3] * SCL;
                }
            } else {
#pragma unroll
                for (int nf = 0; nf < 8; nf++)
#pragma unroll
                    for (int r = 0; r < 4; r++) s[mf][nf][r] *= SCL;
            }

            float ml0 = -INFINITY, ml1 = -INFINITY;
#pragma unroll
            for (int nf = 0; nf < 8; nf++) {
                ml0 = fmaxf(ml0, fmaxf(s[mf][nf][0], s[mf][nf][1]));
                ml1 = fmaxf(ml1, fmaxf(s[mf][nf][2], s[mf][nf][3]));
            }
            ml0 = fmaxf(ml0, __shfl_xor_sync(0xffffffffu, ml0, 1));
            ml0 = fmaxf(ml0, __shfl_xor_sync(0xffffffffu, ml0, 2));
            ml1 = fmaxf(ml1, __shfl_xor_sync(0xffffffffu, ml1, 1));
            ml1 = fmaxf(ml1, __shfl_xor_sync(0xffffffffu, ml1, 2));

            float mn0 = fmaxf(mx[mf][0], ml0), mn1 = fmaxf(mx[mf][1], ml1);
            float al0 = fexp2(mx[mf][0] - mn0), al1 = fexp2(mx[mf][1] - mn1);
            float ls0 = 0.f, ls1 = 0.f;
#pragma unroll
            for (int nf = 0; nf < 8; nf++) {
                s[mf][nf][0] = fexp2(s[mf][nf][0] - mn0);
                s[mf][nf][1] = fexp2(s[mf][nf][1] - mn0);
                s[mf][nf][2] = fexp2(s[mf][nf][2] - mn1);
                s[mf][nf][3] = fexp2(s[mf][nf][3] - mn1);
                ls0 += s[mf][nf][0] + s[mf][nf][1];
                ls1 += s[mf][nf][2] + s[mf][nf][3];
            }
            ls0 += __shfl_xor_sync(0xffffffffu, ls0, 1);
            ls0 += __shfl_xor_sync(0xffffffffu, ls0, 2);
            ls1 += __shfl_xor_sync(0xffffffffu, ls1, 1);
            ls1 += __shfl_xor_sync(0xffffffffu, ls1, 2);

            lsum[mf][0] = lsum[mf][0] * al0 + ls0;
            lsum[mf][1] = lsum[mf][1] * al1 + ls1;
            mx[mf][0] = mn0; mx[mf][1] = mn1;
#pragma unroll
            for (int dn = 0; dn < 8; dn++) {
                o_acc[mf][dn][0] *= al0; o_acc[mf][dn][1] *= al0;
                o_acc[mf][dn][2] *= al1; o_acc[mf][dn][3] *= al1;
            }
        }

        // O += P V  (P fragments via intra-quad shuffles, no SMEM roundtrip)
        const int srcA = (lane & ~3) | (q >> 1);
        const int srcB = srcA + 2;
        const bool odd = (q & 1) != 0;
#pragma unroll
        for (int nf = 0; nf < 8; nf++) {
            uint32_t bv[8][2];
#pragma unroll
            for (int dn = 0; dn < 8; dn++) {
                bv[dn][0] = __float_as_uint(Vb[(nf * 8 + q) * VSTR + dn * 8 + g]);
                bv[dn][1] = __float_as_uint(Vb[(nf * 8 + q + 4) * VSTR + dn * 8 + g]);
            }
#pragma unroll
            for (int mf = 0; mf < 2; mf++) {
                float x0 = __shfl_sync(0xffffffffu, s[mf][nf][0], srcA);
                float x1 = __shfl_sync(0xffffffffu, s[mf][nf][1], srcA);
                float x2 = __shfl_sync(0xffffffffu, s[mf][nf][2], srcA);
                float x3 = __shfl_sync(0xffffffffu, s[mf][nf][3], srcA);
                float y0 = __shfl_sync(0xffffffffu, s[mf][nf][0], srcB);
                float y1 = __shfl_sync(0xffffffffu, s[mf][nf][1], srcB);
                float y2 = __shfl_sync(0xffffffffu, s[mf][nf][2], srcB);
                float y3 = __shfl_sync(0xffffffffu, s[mf][nf][3], srcB);
                uint32_t a[4];
                a[0] = f2tf32u(odd ? x1 : x0);
                a[1] = f2tf32u(odd ? x3 : x2);
                a[2] = f2tf32u(odd ? y1 : y0);
                a[3] = f2tf32u(odd ? y3 : y2);
#pragma unroll
                for (int dn = 0; dn < 8; dn++)
                    mma_m16n8k8(o_acc[mf][dn], a, bv[dn]);
            }
        }
        __syncthreads();
        buf ^= 1;
    }

    // epilogue: normalize, write g_o [B,T,H*64], tf32-rounded for out-proj
    const int bb = bh >> 4, h = bh & 15;
#pragma unroll
    for (int mf = 0; mf < 2; mf++) {
        float inv0 = 1.f / lsum[mf][0], inv1 = 1.f / lsum[mf][1];
        int t0 = qb + w * 32 + mf * 16 + g;
#pragma unroll
        for (int dn = 0; dn < 8; dn++) {
            int col = h * DH_ + dn * 8 + 2 * q;
            size_t o0 = ((size_t)bb * T_ + t0) * DM_ + col;
            size_t o1 = o0 + (size_t)8 * DM_;
            g_o[o0]     = f2tf32(o_acc[mf][dn][0] * inv0);
            g_o[o0 + 1] = f2tf32(o_acc[mf][dn][1] * inv0);
            g_o[o1]     = f2tf32(o_acc[mf][dn][2] * inv1);
            g_o[o1 + 1] = f2tf32(o_acc[mf][dn][3] * inv1);
        }
    }
}

}  // namespace

extern "C" void kernel_launch(void* const* d_in, const int* in_sizes, int n_in,
                              void* d_out, int out_size)
{
    (void)in_sizes; (void)n_in; (void)out_size;
    const float* x  = (const float*)d_in[0];
    const float* Wq = (const float*)d_in[1];
    const float* Wk = (const float*)d_in[2];
    const float* Wv = (const float*)d_in[3];
    const float* Wo = (const float*)d_in[4];
    const float* bo = (const float*)d_in[5];
    float* out = (float*)d_out;

    cudaFuncSetAttribute(gemm2, cudaFuncAttributeMaxDynamicSharedMemorySize, GEMM_SMEM);
    cudaFuncSetAttribute(attn2, cudaFuncAttributeMaxDynamicSharedMemorySize, ATT_SMEM);

    // pre-round to tf32
    round_k<<<(M_ * DM_ / 4 + 255) / 256, 256>>>(x, 0, M_ * DM_ / 4);
    const int wn4 = H_ * DM_ * DH_ / 4;
    round_k<<<(wn4 + 255) / 256, 256>>>(Wq, 1, wn4);
    round_k<<<(wn4 + 255) / 256, 256>>>(Wk, 2, wn4);
    round_k<<<(wn4 + 255) / 256, 256>>>(Wv, 3, wn4);
    round_k<<<(DM_ * DM_ / 4 + 255) / 256, 256>>>(Wo, 4, DM_ * DM_ / 4);

    // fused QKV projections
    gemm2<<<dim3(M_ / 128, DM_ / 128, 3), 256, GEMM_SMEM>>>(0, nullptr, nullptr);
    // causal flash attention
    attn2<<<dim3(T_ / 256, B_ * H_), 256, ATT_SMEM>>>();
    // output projection + bias
    gemm2<<<dim3(M_ / 128, DM_ / 128, 1), 256, GEMM_SMEM>>>(1, bo, out);
}

// round 5
// speedup vs baseline: 1.4076x; 1.0435x over previous
#include <cuda_runtime.h>
#include <cstdint>
#include <math.h>

namespace {
constexpr int B_  = 4;
constexpr int T_  = 2048;
constexpr int DM_ = 1024;
constexpr int H_  = 16;
constexpr int DH_ = 64;
constexpr int M_  = B_ * T_;     // 8192

// Scratch (device globals: allocation-free rule). All tf32-pre-rounded copies.
__device__ float g_x [(size_t)M_ * DM_];
__device__ float g_wq[(size_t)H_ * DM_ * DH_];
__device__ float g_wk[(size_t)H_ * DM_ * DH_];
__device__ float g_wv[(size_t)H_ * DM_ * DH_];
__device__ float g_wo[(size_t)DM_ * DM_];
__device__ float g_q [(size_t)M_ * DM_];   // [B,H,T,64]
__device__ float g_k [(size_t)M_ * DM_];
__device__ float g_v [(size_t)M_ * DM_];
__device__ float g_o [(size_t)M_ * DM_];   // [B,T,H*64]

__device__ __forceinline__ float f2tf32(float x) {
    uint32_t u;
    asm("cvt.rna.tf32.f32 %0, %1;" : "=r"(u) : "f"(x));
    return __uint_as_float(u);
}
__device__ __forceinline__ uint32_t f2tf32u(float x) {
    uint32_t u;
    asm("cvt.rna.tf32.f32 %0, %1;" : "=r"(u) : "f"(x));
    return u;
}
__device__ __forceinline__ float fexp2(float x) {
    float y;
    asm("ex2.approx.f32 %0, %1;" : "=f"(y) : "f"(x));
    return y;
}
__device__ __forceinline__ void mma_m16n8k8(float* c, const uint32_t* a, const uint32_t* b) {
    asm volatile(
        "mma.sync.aligned.m16n8k8.row.col.f32.tf32.tf32.f32 "
        "{%0,%1,%2,%3}, {%4,%5,%6,%7}, {%8,%9}, {%0,%1,%2,%3};\n"
        : "+f"(c[0]), "+f"(c[1]), "+f"(c[2]), "+f"(c[3])
        : "r"(a[0]), "r"(a[1]), "r"(a[2]), "r"(a[3]), "r"(b[0]), "r"(b[1]));
}
__device__ __forceinline__ uint32_t smem_u32(const void* p) {
    return (uint32_t)__cvta_generic_to_shared(p);
}
__device__ __forceinline__ void cp16(uint32_t dst, const void* src) {
    asm volatile("cp.async.cg.shared.global [%0], [%1], 16;\n" :: "r"(dst), "l"(src));
}
__device__ __forceinline__ void cp_commit() {
    asm volatile("cp.async.commit_group;\n");
}
template <int N>
__device__ __forceinline__ void cp_wait() {
    asm volatile("cp.async.wait_group %0;\n" :: "n"(N));
}

// ---------------------------------------------------------------------------
// Pre-round fp32 -> tf32 copies (so cp.async can move pre-rounded data)
// ---------------------------------------------------------------------------
__global__ void __launch_bounds__(256) round_k(const float* __restrict__ in, int which, int n4)
{
    float* out = (which == 0) ? g_x  : (which == 1) ? g_wq :
                 (which == 2) ? g_wk : (which == 3) ? g_wv : g_wo;
    int i = blockIdx.x * blockDim.x + threadIdx.x;
    if (i < n4) {
        float4 v = reinterpret_cast<const float4*>(in)[i];
        reinterpret_cast<float4*>(out)[i] =
            make_float4(f2tf32(v.x), f2tf32(v.y), f2tf32(v.z), f2tf32(v.w));
    }
}

// ---------------------------------------------------------------------------
// GEMM, tile 128x128, warp 32x64, k-chunk 32, 3-stage cp.async pipeline,
// single barrier per k-iter.
// mode 0: QKV projection. grid (64, 8, 3). z selects Wq/Wk/Wv.
// mode 1: out projection. grid (64, 8, 1). X=g_o, W=g_wo, out=d_out + bias.
// ---------------------------------------------------------------------------
constexpr int XSTR = 36;    // 32 + 4 pad (floats)
constexpr int WSTR = 136;   // 128 + 8 pad (floats)
constexpr int NSTG = 3;
constexpr int GSTAGE = 128 * XSTR + 32 * WSTR;    // 8960 floats (35840 B)
constexpr int GEMM_SMEM = NSTG * GSTAGE * 4;      // 107520 B

__device__ __forceinline__ void gemm_load_chunk(
    float* sm, int buf, const float* __restrict__ X, const float* __restrict__ W,
    size_t mBase, int by, int k0, int mode, int tid)
{
    float* Xb = sm + buf * GSTAGE;
    float* Wb = Xb + 128 * XSTR;
#pragma unroll
    for (int i = 0; i < 4; i++) {
        int idx = tid + i * 256;
        int r = idx >> 3, c4 = (idx & 7) * 4;
        cp16(smem_u32(Xb + r * XSTR + c4), X + (mBase + r) * DM_ + k0 + c4);
    }
#pragma unroll
    for (int i = 0; i < 4; i++) {
        int idx = tid + i * 256;
        int r = idx >> 5, c4 = (idx & 31) * 4;
        const float* src;
        if (mode == 0) {
            int c = by * 128 + c4;
            int h = c >> 6;
            src = W + ((size_t)h * DM_ + (k0 + r)) * DH_ + (c & 63);
        } else {
            src = W + (size_t)(k0 + r) * DM_ + by * 128 + c4;
        }
        cp16(smem_u32(Wb + r * WSTR + c4), src);
    }
    cp_commit();
}

__global__ void __launch_bounds__(256, 2) gemm2(
    int mode, const float* __restrict__ bias, float* __restrict__ out_param)
{
    extern __shared__ float sm[];
    const int tid  = threadIdx.x;
    const int lane = tid & 31, wid = tid >> 5;
    const int wm = wid >> 1, wn = wid & 1;
    const int g = lane >> 2, q = lane & 3;
    const size_t mBase = (size_t)blockIdx.x * 128;
    const int by = blockIdx.y;
    const int z  = blockIdx.z;
    constexpr int NCHUNK = DM_ / 32;   // 32

    const float* X = (mode == 0) ? g_x : g_o;
    const float* W = (mode == 0) ? ((z == 0) ? g_wq : (z == 1) ? g_wk : g_wv) : g_wo;

    float acc[2][8][4];
#pragma unroll
    for (int i = 0; i < 2; i++)
#pragma unroll
        for (int j = 0; j < 8; j++)
#pragma unroll
            for (int r = 0; r < 4; r++) acc[i][j][r] = 0.f;

    gemm_load_chunk(sm, 0, X, W, mBase, by, 0, mode, tid);
    gemm_load_chunk(sm, 1, X, W, mBase, by, 32, mode, tid);

#pragma unroll 1
    for (int i = 0; i < NCHUNK; i++) {
        if (i + 1 < NCHUNK) cp_wait<1>(); else cp_wait<0>();
        __syncthreads();   // chunk i resident; all warps past compute(i-1)
        if (i + 2 < NCHUNK)
            gemm_load_chunk(sm, (i + 2) % NSTG, X, W, mBase, by, (i + 2) * 32, mode, tid);

        const float* Xb = sm + (i % NSTG) * GSTAGE;
        const float* Wb = Xb + 128 * XSTR;
#pragma unroll
        for (int ks = 0; ks < 4; ks++) {
            uint32_t a[2][4];
#pragma unroll
            for (int mf = 0; mf < 2; mf++) {
                const float* xr = Xb + (wm * 32 + mf * 16 + g) * XSTR + ks * 8 + q;
                a[mf][0] = __float_as_uint(xr[0]);
                a[mf][1] = __float_as_uint(xr[8 * XSTR]);
                a[mf][2] = __float_as_uint(xr[4]);
                a[mf][3] = __float_as_uint(xr[8 * XSTR + 4]);
            }
            uint32_t b[8][2];
#pragma unroll
            for (int nf = 0; nf < 8; nf++) {
                int n = wn * 64 + nf * 8 + g;
                b[nf][0] = __float_as_uint(Wb[(ks * 8 + q) * WSTR + n]);
                b[nf][1] = __float_as_uint(Wb[(ks * 8 + q + 4) * WSTR + n]);
            }
#pragma unroll
            for (int mf = 0; mf < 2; mf++)
#pragma unroll
                for (int nf = 0; nf < 8; nf++)
                    mma_m16n8k8(acc[mf][nf], a[mf], b[nf]);
        }
    }

    if (mode == 0) {
        float* outp = (z == 0) ? g_q : (z == 1) ? g_k : g_v;
#pragma unroll
        for (int mf = 0; mf < 2; mf++)
#pragma unroll
            for (int rr = 0; rr < 2; rr++) {
                size_t row = mBase + wm * 32 + mf * 16 + g + rr * 8;
                int bb = (int)(row >> 11), t = (int)(row & 2047);
#pragma unroll
                for (int nf = 0; nf < 8; nf++) {
                    int c = by * 128 + wn * 64 + nf * 8 + 2 * q;
                    int h = c >> 6, cc = c & 63;
                    size_t o = (((size_t)bb * H_ + h) * T_ + t) * DH_ + cc;
                    outp[o]     = f2tf32(acc[mf][nf][2 * rr + 0]);
                    outp[o + 1] = f2tf32(acc[mf][nf][2 * rr + 1]);
                }
            }
    } else {
#pragma unroll
        for (int mf = 0; mf < 2; mf++)
#pragma unroll
            for (int rr = 0; rr < 2; rr++) {
                size_t row = mBase + wm * 32 + mf * 16 + g + rr * 8;
#pragma unroll
                for (int nf = 0; nf < 8; nf++) {
                    int c = by * 128 + wn * 64 + nf * 8 + 2 * q;
                    size_t o = row * DM_ + c;
                    out_param[o]     = acc[mf][nf][2 * rr + 0] + bias[c];
                    out_param[o + 1] = acc[mf][nf][2 * rr + 1] + bias[c + 1];
                }
            }
    }
}

// ---------------------------------------------------------------------------
// Causal flash attention. CTA = 256 Q rows (8 warps x 32 rows), key blocks
// of 64, 3-stage cp.async KV pipeline (single barrier/iter), Q frags in
// registers pre-scaled by 0.125*log2(e), P via shuffles (no cvt).
// grid (T/256=8, B*H=64), 256 threads.
// ---------------------------------------------------------------------------
constexpr int KSTR = 68;    // 64 + 4 pad
constexpr int VSTR = 72;    // 64 + 8 pad
constexpr int ASTAGE = 64 * KSTR + 64 * VSTR;    // 8960 floats
constexpr int ATT_SMEM = NSTG * ASTAGE * 4;      // 107520 B

__device__ __forceinline__ void attn_load_kv(
    float* sm, int buf, const float* __restrict__ Kg, const float* __restrict__ Vg,
    int j, int tid)
{
    float* Kb = sm + buf * ASTAGE;
    float* Vb = Kb + 64 * KSTR;
#pragma unroll
    for (int i = 0; i < 4; i++) {
        int idx = tid + i * 256;
        int r = idx >> 4, c4 = (idx & 15) * 4;
        cp16(smem_u32(Kb + r * KSTR + c4), Kg + (size_t)(j * 64 + r) * DH_ + c4);
    }
#pragma unroll
    for (int i = 0; i < 4; i++) {
        int idx = tid + i * 256;
        int r = idx >> 4, c4 = (idx & 15) * 4;
        cp16(smem_u32(Vb + r * VSTR + c4), Vg + (size_t)(j * 64 + r) * DH_ + c4);
    }
    cp_commit();
}

__global__ void __launch_bounds__(256, 1) attn2()
{
    extern __shared__ float sm[];
    const int tid  = threadIdx.x;
    const int lane = tid & 31, w = tid >> 5;
    const int g = lane >> 2, q = lane & 3;
    const int bx = (int)gridDim.x - 1 - (int)blockIdx.x;   // heavy CTAs first
    const int bh = blockIdx.y;
    const int qb = bx * 256;
    const float SCL = 0.18033688f;   // 0.125 * log2(e), folded into Q

    const float* Qg = g_q + ((size_t)bh * T_ + qb) * DH_;
    const float* Kg = g_k + (size_t)bh * T_ * DH_;
    const float* Vg = g_v + (size_t)bh * T_ * DH_;

    // Q fragments -> registers, pre-scaled + re-rounded to tf32
    uint32_t qf[2][8][4];
#pragma unroll
    for (int mf = 0; mf < 2; mf++) {
        int r = w * 32 + mf * 16 + g;
#pragma unroll
        for (int ks = 0; ks < 8; ks++) {
            qf[mf][ks][0] = f2tf32u(__ldg(Qg + (size_t)r * DH_ + ks * 8 + q) * SCL);
            qf[mf][ks][1] = f2tf32u(__ldg(Qg + (size_t)(r + 8) * DH_ + ks * 8 + q) * SCL);
            qf[mf][ks][2] = f2tf32u(__ldg(Qg + (size_t)r * DH_ + ks * 8 + q + 4) * SCL);
            qf[mf][ks][3] = f2tf32u(__ldg(Qg + (size_t)(r + 8) * DH_ + ks * 8 + q + 4) * SCL);
        }
    }

    float o_acc[2][8][4];
#pragma unroll
    for (int i = 0; i < 2; i++)
#pragma unroll
        for (int j = 0; j < 8; j++)
#pragma unroll
            for (int r = 0; r < 4; r++) o_acc[i][j][r] = 0.f;
    float mx[2][2] = {{-INFINITY, -INFINITY}, {-INFINITY, -INFINITY}};
    float lsum[2][2] = {{0.f, 0.f}, {0.f, 0.f}};

    const int nkb = 4 * bx + 4;
    attn_load_kv(sm, 0, Kg, Vg, 0, tid);
    attn_load_kv(sm, 1, Kg, Vg, 1, tid);

#pragma unroll 1
    for (int j = 0; j < nkb; j++) {
        if (j + 1 < nkb) cp_wait<1>(); else cp_wait<0>();
        __syncthreads();   // chunk j resident; all warps past compute(j-1)
        if (j + 2 < nkb) attn_load_kv(sm, (j + 2) % NSTG, Kg, Vg, j + 2, tid);

        const float* Kb = sm + (j % NSTG) * ASTAGE;
        const float* Vb = Kb + 64 * KSTR;

        // S = (Q*scl) K^T : per warp 32x64 (already in log2-softmax domain)
        float s[2][8][4];
#pragma unroll
        for (int i = 0; i < 2; i++)
#pragma unroll
            for (int jj = 0; jj < 8; jj++)
#pragma unroll
                for (int r = 0; r < 4; r++) s[i][jj][r] = 0.f;

#pragma unroll
        for (int ks = 0; ks < 8; ks++) {
            uint32_t bk[8][2];
#pragma unroll
            for (int nf = 0; nf < 8; nf++) {
                bk[nf][0] = __float_as_uint(Kb[(nf * 8 + g) * KSTR + ks * 8 + q]);
                bk[nf][1] = __float_as_uint(Kb[(nf * 8 + g) * KSTR + ks * 8 + q + 4]);
            }
#pragma unroll
            for (int mf = 0; mf < 2; mf++)
#pragma unroll
                for (int nf = 0; nf < 8; nf++)
                    mma_m16n8k8(s[mf][nf], qf[mf][ks], bk[nf]);
        }

        // causal mask (diagonal blocks only) + online softmax
        const bool need_mask = (j * 64 + 63) > (qb + w * 32);
#pragma unroll
        for (int mf = 0; mf < 2; mf++) {
            const int row0 = qb + w * 32 + mf * 16 + g;
            if (need_mask) {
#pragma unroll
                for (int nf = 0; nf < 8; nf++) {
                    int c0 = j * 64 + nf * 8 + 2 * q;
                    if (c0     > row0)     s[mf][nf][0] = -INFINITY;
                    if (c0 + 1 > row0)     s[mf][nf][1] = -INFINITY;
                    if (c0     > row0 + 8) s[mf][nf][2] = -INFINITY;
                    if (c0 + 1 > row0 + 8) s[mf][nf][3] = -INFINITY;
                }
            }

            float ml0 = -INFINITY, ml1 = -INFINITY;
#pragma unroll
            for (int nf = 0; nf < 8; nf++) {
                ml0 = fmaxf(ml0, fmaxf(s[mf][nf][0], s[mf][nf][1]));
                ml1 = fmaxf(ml1, fmaxf(s[mf][nf][2], s[mf][nf][3]));
            }
            ml0 = fmaxf(ml0, __shfl_xor_sync(0xffffffffu, ml0, 1));
            ml0 = fmaxf(ml0, __shfl_xor_sync(0xffffffffu, ml0, 2));
            ml1 = fmaxf(ml1, __shfl_xor_sync(0xffffffffu, ml1, 1));
            ml1 = fmaxf(ml1, __shfl_xor_sync(0xffffffffu, ml1, 2));

            float mn0 = fmaxf(mx[mf][0], ml0), mn1 = fmaxf(mx[mf][1], ml1);
            float al0 = fexp2(mx[mf][0] - mn0), al1 = fexp2(mx[mf][1] - mn1);
            float ls0 = 0.f, ls1 = 0.f;
#pragma unroll
            for (int nf = 0; nf < 8; nf++) {
                s[mf][nf][0] = fexp2(s[mf][nf][0] - mn0);
                s[mf][nf][1] = fexp2(s[mf][nf][1] - mn0);
                s[mf][nf][2] = fexp2(s[mf][nf][2] - mn1);
                s[mf][nf][3] = fexp2(s[mf][nf][3] - mn1);
                ls0 += s[mf][nf][0] + s[mf][nf][1];
                ls1 += s[mf][nf][2] + s[mf][nf][3];
            }
            ls0 += __shfl_xor_sync(0xffffffffu, ls0, 1);
            ls0 += __shfl_xor_sync(0xffffffffu, ls0, 2);
            ls1 += __shfl_xor_sync(0xffffffffu, ls1, 1);
            ls1 += __shfl_xor_sync(0xffffffffu, ls1, 2);

            lsum[mf][0] = lsum[mf][0] * al0 + ls0;
            lsum[mf][1] = lsum[mf][1] * al1 + ls1;
            mx[mf][0] = mn0; mx[mf][1] = mn1;
#pragma unroll
            for (int dn = 0; dn < 8; dn++) {
                o_acc[mf][dn][0] *= al0; o_acc[mf][dn][1] *= al0;
                o_acc[mf][dn][2] *= al1; o_acc[mf][dn][3] *= al1;
            }
        }

        // O += P V  (P fragments via intra-quad shuffles; HW truncation to tf32)
        const int srcA = (lane & ~3) | (q >> 1);
        const int srcB = srcA + 2;
        const bool odd = (q & 1) != 0;
#pragma unroll
        for (int nf = 0; nf < 8; nf++) {
            uint32_t bv[8][2];
#pragma unroll
            for (int dn = 0; dn < 8; dn++) {
                bv[dn][0] = __float_as_uint(Vb[(nf * 8 + q) * VSTR + dn * 8 + g]);
                bv[dn][1] = __float_as_uint(Vb[(nf * 8 + q + 4) * VSTR + dn * 8 + g]);
            }
#pragma unroll
            for (int mf = 0; mf < 2; mf++) {
                float x0 = __shfl_sync(0xffffffffu, s[mf][nf][0], srcA);
                float x1 = __shfl_sync(0xffffffffu, s[mf][nf][1], srcA);
                float x2 = __shfl_sync(0xffffffffu, s[mf][nf][2], srcA);
                float x3 = __shfl_sync(0xffffffffu, s[mf][nf][3], srcA);
                float y0 = __shfl_sync(0xffffffffu, s[mf][nf][0], srcB);
                float y1 = __shfl_sync(0xffffffffu, s[mf][nf][1], srcB);
                float y2 = __shfl_sync(0xffffffffu, s[mf][nf][2], srcB);
                float y3 = __shfl_sync(0xffffffffu, s[mf][nf][3], srcB);
                uint32_t a[4];
                a[0] = __float_as_uint(odd ? x1 : x0);
                a[1] = __float_as_uint(odd ? x3 : x2);
                a[2] = __float_as_uint(odd ? y1 : y0);
                a[3] = __float_as_uint(odd ? y3 : y2);
#pragma unroll
                for (int dn = 0; dn < 8; dn++)
                    mma_m16n8k8(o_acc[mf][dn], a, bv[dn]);
            }
        }
        // no trailing barrier: next iter's top barrier protects slot reuse
    }

    // epilogue: normalize, write g_o [B,T,H*64], tf32-rounded for out-proj
    const int bb = bh >> 4, h = bh & 15;
#pragma unroll
    for (int mf = 0; mf < 2; mf++) {
        float inv0 = 1.f / lsum[mf][0], inv1 = 1.f / lsum[mf][1];
        int t0 = qb + w * 32 + mf * 16 + g;
#pragma unroll
        for (int dn = 0; dn < 8; dn++) {
            int col = h * DH_ + dn * 8 + 2 * q;
            size_t o0 = ((size_t)bb * T_ + t0) * DM_ + col;
            size_t o1 = o0 + (size_t)8 * DM_;
            g_o[o0]     = f2tf32(o_acc[mf][dn][0] * inv0);
            g_o[o0 + 1] = f2tf32(o_acc[mf][dn][1] * inv0);
            g_o[o1]     = f2tf32(o_acc[mf][dn][2] * inv1);
            g_o[o1 + 1] = f2tf32(o_acc[mf][dn][3] * inv1);
        }
    }
}

}  // namespace

extern "C" void kernel_launch(void* const* d_in, const int* in_sizes, int n_in,
                              void* d_out, int out_size)
{
    (void)in_sizes; (void)n_in; (void)out_size;
    const float* x  = (const float*)d_in[0];
    const float* Wq = (const float*)d_in[1];
    const float* Wk = (const float*)d_in[2];
    const float* Wv = (const float*)d_in[3];
    const float* Wo = (const float*)d_in[4];
    const float* bo = (const float*)d_in[5];
    float* out = (float*)d_out;

    cudaFuncSetAttribute(gemm2, cudaFuncAttributeMaxDynamicSharedMemorySize, GEMM_SMEM);
    cudaFuncSetAttribute(attn2, cudaFuncAttributeMaxDynamicSharedMemorySize, ATT_SMEM);

    // pre-round to tf32
    round_k<<<(M_ * DM_ / 4 + 255) / 256, 256>>>(x, 0, M_ * DM_ / 4);
    const int wn4 = H_ * DM_ * DH_ / 4;
    round_k<<<(wn4 + 255) / 256, 256>>>(Wq, 1, wn4);
    round_k<<<(wn4 + 255) / 256, 256>>>(Wk, 2, wn4);
    round_k<<<(wn4 + 255) / 256, 256>>>(Wv, 3, wn4);
    round_k<<<(DM_ * DM_ / 4 + 255) / 256, 256>>>(Wo, 4, DM_ * DM_ / 4);

    // fused QKV projections
    gemm2<<<dim3(M_ / 128, DM_ / 128, 3), 256, GEMM_SMEM>>>(0, nullptr, nullptr);
    // causal flash attention
    attn2<<<dim3(T_ / 256, B_ * H_), 256, ATT_SMEM>>>();
    // output projection + bias
    gemm2<<<dim3(M_ / 128, DM_ / 128, 1), 256, GEMM_SMEM>>>(1, bo, out);
}